// round 16
// baseline (speedup 1.0000x reference)
#include <cuda_runtime.h>
#include <cuda_fp16.h>
#include <cstdint>

// ---------------------------------------------------------------------------
// SelfAttention on GB300 (sm_103 base target).
// R16: hybrid fragment paths. 3-product GEMMs (Q/K-proj, scores) identical to
// R15 (A-ldsm + scalar B; at the register ceiling). 1-product GEMMs (V-proj,
// attn, out) consume B in BT format ([n][k/2] k-contiguous) via ldmatrix.x4 —
// low register pressure makes dual-ldsm safe there. Kchunk = 128.
// ---------------------------------------------------------------------------

#define BATCH 4
#define DDIM  1024
#define NSEQ  2048
#define MH    1024
#define MV    1024

// ---- packed global scratch (uint32 = f16x2). Allocation-free contract. ----
__device__ __align__(256) uint32_t g_xBh[(size_t)BATCH * (DDIM/2) * NSEQ];
__device__ __align__(256) uint32_t g_xBl[(size_t)BATCH * (DDIM/2) * NSEQ];
__device__ __align__(256) uint32_t g_xTh[(size_t)BATCH * NSEQ * (DDIM/2)];   // x^T BT (hi)
__device__ __align__(256) uint32_t g_wqh[(size_t)MH * (DDIM/2)];
__device__ __align__(256) uint32_t g_wql[(size_t)MH * (DDIM/2)];
__device__ __align__(256) uint32_t g_wkh[(size_t)MH * (DDIM/2)];
__device__ __align__(256) uint32_t g_wkl[(size_t)MH * (DDIM/2)];
__device__ __align__(256) uint32_t g_wvh[(size_t)MV * (DDIM/2)];
__device__ __align__(256) uint32_t g_woh[(size_t)DDIM * (MV/2)];
__device__ __align__(256) uint32_t g_qBh[(size_t)BATCH * (MH/2) * NSEQ];
__device__ __align__(256) uint32_t g_qBl[(size_t)BATCH * (MH/2) * NSEQ];
__device__ __align__(256) uint32_t g_ktAh[(size_t)BATCH * NSEQ * (MH/2)];
__device__ __align__(256) uint32_t g_ktAl[(size_t)BATCH * NSEQ * (MH/2)];
__device__ __align__(256) uint32_t g_vAh[(size_t)BATCH * MV * (NSEQ/2)];
__device__ __align__(256) uint32_t g_vAl[(size_t)BATCH * MV * (NSEQ/2)];
__device__ __align__(256) float    g_s[(size_t)BATCH * NSEQ * NSEQ];
__device__ __align__(256) uint32_t g_sBh[(size_t)BATCH * (NSEQ/2) * NSEQ];
__device__ __align__(256) uint32_t g_sT[(size_t)BATCH * NSEQ * (NSEQ/2)];    // S^T BT
__device__ __align__(256) uint32_t g_aTh[(size_t)BATCH * NSEQ * (MV/2)];     // attn^T BT
__device__ __align__(256) uint32_t g_aTl[(size_t)BATCH * NSEQ * (MV/2)];

// ---- helpers ----
__device__ __forceinline__ uint32_t pack2(float a, float b) {
    __half2 h = __halves2half2(__float2half_rn(a), __float2half_rn(b));
    return *reinterpret_cast<uint32_t*>(&h);
}
__device__ __forceinline__ void splitpack(float x0, float x1, uint32_t& hw, uint32_t& lw) {
    float h0 = __half2float(__float2half_rn(x0));
    float h1 = __half2float(__float2half_rn(x1));
    hw = pack2(h0, h1);
    lw = pack2(x0 - h0, x1 - h1);
}
__device__ __forceinline__ void mma_f16(float* c, const uint32_t* a, const uint32_t* b) {
    asm volatile(
        "mma.sync.aligned.m16n8k16.row.col.f32.f16.f16.f32 "
        "{%0,%1,%2,%3}, {%4,%5,%6,%7}, {%8,%9}, {%0,%1,%2,%3};"
        : "+f"(c[0]), "+f"(c[1]), "+f"(c[2]), "+f"(c[3])
        : "r"(a[0]), "r"(a[1]), "r"(a[2]), "r"(a[3]), "r"(b[0]), "r"(b[1]));
}
__device__ __forceinline__ void ldsm_x4(uint32_t* r, uint32_t addr) {
    asm volatile("ldmatrix.sync.aligned.m8n8.x4.shared.b16 {%0,%1,%2,%3}, [%4];"
        : "=r"(r[0]), "=r"(r[1]), "=r"(r[2]), "=r"(r[3]) : "r"(addr));
}
__device__ __forceinline__ uint32_t smem_u32(const void* p) {
    uint32_t a;
    asm("{ .reg .u64 t; cvta.to.shared.u64 t, %1; cvt.u32.u64 %0, t; }" : "=r"(a) : "l"(p));
    return a;
}
__device__ __forceinline__ void cpa16(uint32_t d, const void* s) {
    asm volatile("cp.async.cg.shared.global [%0], [%1], 16;" :: "r"(d), "l"(s));
}

// ---- smem layout (word offsets), single stage, Kchunk = 128 elems = 64 words ----
#define PAW 68      // pitch: 64 words + 4 pad (ldsm CF: 272B = 17*16B, 17 mod 8 = 1)
#define PBW 72      // scalar-B pitch (3-product path)
#define SA_H 0
#define SA_L 8704   // 128*68
#define SB_H 17408
#define SB_L 22016  // +64*72
#define SMEM_WORDS 26624
#define SMEM_BYTES (SMEM_WORDS * 4)   // 106496 B -> 2 CTAs/SM

// Epilogue modes
#define EPI_PLAIN 0
#define EPI_A     1
#define EPI_B     2
#define EPI_AT    3

// ---------------------------------------------------------------------------
// C[m,n] = sum_k A(m,k)B(k,n); packed f16x2 hi/lo operands.
// A: [m][k/2] words (stride sAw).
// B: BT=false -> [k/2][n] words (stride sBw);  BT=true -> [n][k/2] (stride sBw).
// NPROD = 3: hi*hi + hi*lo + lo*hi.  NPROD = 1: hi*hi only (BT requires NPROD=1).
// Tile 128(M) x 64(N) x 128(K). 256 thr, 8 warps (4m x 2n), warp tile 32x32.
// ---------------------------------------------------------------------------
template <int EPI, int NPROD, bool BT>
__global__ void __launch_bounds__(256, 2)
gemm16(const uint32_t* __restrict__ Ah, const uint32_t* __restrict__ Al,
       const uint32_t* __restrict__ Bh, const uint32_t* __restrict__ Bl,
       float* __restrict__ Cf, uint32_t* __restrict__ Ch, uint32_t* __restrict__ Cl,
       int K, long long sAw, long long sBw, long long ldC,
       long long bA, long long bB, long long bC)
{
    extern __shared__ uint32_t smw[];
    const uint32_t smb = smem_u32(smw);

    const int tid = threadIdx.x, wid = tid >> 5, lane = tid & 31;
    const int gid = lane >> 2, tig = lane & 3;
    const int wm = (wid & 3) << 5;
    const int wn = (wid >> 2) << 5;

    const uint32_t* Abh = Ah + (long long)blockIdx.z * bA;
    const uint32_t* Abl = (NPROD == 3) ? Al + (long long)blockIdx.z * bA : nullptr;
    const uint32_t* Bbh = Bh + (long long)blockIdx.z * bB;
    const uint32_t* Bbl = (NPROD == 3) ? Bl + (long long)blockIdx.z * bB : nullptr;
    const long long bm = (long long)blockIdx.y << 7;
    const long long bn = (long long)blockIdx.x << 6;

    const int lrow = (lane & 7) + (((lane >> 3) & 1) << 3);   // A ldsm row
    const int lcol = ((lane >> 4) & 1) << 2;                  // A ldsm col
    const int brow = (lane & 7) + ((lane >> 4) << 3);         // B ldsm row (BT)
    const int bcol = ((lane >> 3) & 1) << 2;                  // B ldsm col (BT)

    float acc[2][4][4];
#pragma unroll
    for (int mt = 0; mt < 2; mt++)
#pragma unroll
        for (int nt = 0; nt < 4; nt++)
#pragma unroll
            for (int r = 0; r < 4; r++) acc[mt][nt][r] = 0.0f;

    const int nch = K >> 7;            // Kchunk = 128 elems = 64 words
    for (int ic = 0; ic < nch; ic++) {
        const long long k0w = (long long)ic << 6;

        // ---- A tile: 128 rows x 64 words ----
#pragma unroll
        for (int i = 0; i < 8; i++) {
            int idx = tid + (i << 8);
            int row = idx >> 4, g4 = (idx & 15) << 2;
            uint32_t d = smb + (uint32_t)((row * PAW + g4) << 2);
            cpa16(d, Abh + (bm + row) * sAw + k0w + g4);
            if (NPROD == 3)
                cpa16(d + (SA_L << 2), Abl + (bm + row) * sAw + k0w + g4);
        }
        // ---- B tile ----
        if (!BT) {
            // [64 k word-rows][64 n words], pitch PBW
#pragma unroll
            for (int i = 0; i < 4; i++) {
                int idx = tid + (i << 8);
                int wr = idx >> 4, g4 = (idx & 15) << 2;
                uint32_t d = smb + (uint32_t)((SB_H + wr * PBW + g4) << 2);
                cpa16(d, Bbh + (k0w + wr) * sBw + bn + g4);
                if (NPROD == 3)
                    cpa16(d + ((SB_L - SB_H) << 2), Bbl + (k0w + wr) * sBw + bn + g4);
            }
        } else {
            // BT: [64 n rows][64 k words], pitch PAW (hi only)
#pragma unroll
            for (int i = 0; i < 4; i++) {
                int idx = tid + (i << 8);
                int row = idx >> 4, g4 = (idx & 15) << 2;
                uint32_t d = smb + (uint32_t)((SB_H + row * PAW + g4) << 2);
                cpa16(d, Bbh + (bn + row) * sBw + k0w + g4);
            }
        }
        asm volatile("cp.async.commit_group;" ::: "memory");
        asm volatile("cp.async.wait_group 0;" ::: "memory");
        __syncthreads();

#pragma unroll
        for (int ks = 0; ks < 8; ks++) {
            const int kb = ks << 3;
            uint32_t ah[2][4], al[2][4], bh[4][2], bl[4][2];
#pragma unroll
            for (int mt = 0; mt < 2; mt++) {
                int row = wm + (mt << 4) + lrow;
                uint32_t ad = smb + (uint32_t)((SA_H + row * PAW + kb + lcol) << 2);
                ldsm_x4(ah[mt], ad);
                if (NPROD == 3) ldsm_x4(al[mt], ad + ((SA_L - SA_H) << 2));
            }
            if (!BT) {
#pragma unroll
                for (int nt = 0; nt < 4; nt++) {
                    int cc = wn + (nt << 3) + gid;
                    bh[nt][0] = smw[SB_H + (kb + tig) * PBW + cc];
                    bh[nt][1] = smw[SB_H + (kb + tig + 4) * PBW + cc];
                    if (NPROD == 3) {
                        bl[nt][0] = smw[SB_L + (kb + tig) * PBW + cc];
                        bl[nt][1] = smw[SB_L + (kb + tig + 4) * PBW + cc];
                    }
                }
            } else {
#pragma unroll
                for (int np = 0; np < 2; np++) {
                    uint32_t bt[4];
                    uint32_t bd = smb + (uint32_t)((SB_H + (wn + (np << 4) + brow) * PAW + kb + bcol) << 2);
                    ldsm_x4(bt, bd);
                    bh[np * 2 + 0][0] = bt[0]; bh[np * 2 + 0][1] = bt[1];
                    bh[np * 2 + 1][0] = bt[2]; bh[np * 2 + 1][1] = bt[3];
                }
            }
#pragma unroll
            for (int mt = 0; mt < 2; mt++)
#pragma unroll
                for (int nt = 0; nt < 4; nt++) mma_f16(acc[mt][nt], ah[mt], bh[nt]);
            if (NPROD == 3) {
#pragma unroll
                for (int mt = 0; mt < 2; mt++)
#pragma unroll
                    for (int nt = 0; nt < 4; nt++) mma_f16(acc[mt][nt], ah[mt], bl[nt]);
#pragma unroll
                for (int mt = 0; mt < 2; mt++)
#pragma unroll
                    for (int nt = 0; nt < 4; nt++) mma_f16(acc[mt][nt], al[mt], bh[nt]);
            }
        }
        __syncthreads();
    }

    // ---------------- epilogues ----------------
    if (EPI == EPI_PLAIN) {
        float* Cb = Cf + (long long)blockIdx.z * bC;
#pragma unroll
        for (int mt = 0; mt < 2; mt++) {
            long long r0 = bm + wm + (mt << 4) + gid;
#pragma unroll
            for (int nt = 0; nt < 4; nt++) {
                long long cc = bn + wn + (nt << 3) + (tig << 1);
                *reinterpret_cast<float2*>(Cb + r0 * ldC + cc)       = make_float2(acc[mt][nt][0], acc[mt][nt][1]);
                *reinterpret_cast<float2*>(Cb + (r0 + 8) * ldC + cc) = make_float2(acc[mt][nt][2], acc[mt][nt][3]);
            }
        }
    } else if (EPI == EPI_A) {
        uint32_t* Cbh = Ch + (long long)blockIdx.z * bC;
        uint32_t* Cbl = Cl + (long long)blockIdx.z * bC;
#pragma unroll
        for (int mt = 0; mt < 2; mt++) {
            long long r0 = bm + wm + (mt << 4) + gid;
#pragma unroll
            for (int nt = 0; nt < 4; nt++) {
                long long wc = (bn + wn + (nt << 3) + (tig << 1)) >> 1;
                uint32_t hw, lw;
                splitpack(acc[mt][nt][0], acc[mt][nt][1], hw, lw);
                Cbh[r0 * ldC + wc] = hw; Cbl[r0 * ldC + wc] = lw;
                splitpack(acc[mt][nt][2], acc[mt][nt][3], hw, lw);
                Cbh[(r0 + 8) * ldC + wc] = hw; Cbl[(r0 + 8) * ldC + wc] = lw;
            }
        }
    } else {
        float* esm = reinterpret_cast<float*>(smw);   // [128m][pitch 65]
        const int PE = 65;
#pragma unroll
        for (int mt = 0; mt < 2; mt++) {
            int r = wm + (mt << 4) + gid;
#pragma unroll
            for (int nt = 0; nt < 4; nt++) {
                int c = wn + (nt << 3) + (tig << 1);
                esm[r * PE + c]           = acc[mt][nt][0];
                esm[r * PE + c + 1]       = acc[mt][nt][1];
                esm[(r + 8) * PE + c]     = acc[mt][nt][2];
                esm[(r + 8) * PE + c + 1] = acc[mt][nt][3];
            }
        }
        __syncthreads();
        uint32_t* Cbh = Ch + (long long)blockIdx.z * bC;
        uint32_t* Cbl = Cl + (long long)blockIdx.z * bC;
        if (EPI == EPI_B) {
            const int n = tid & 63, grp = tid >> 6;
#pragma unroll
            for (int j = 0; j < 16; j++) {
                int wr = grp * 16 + j;
                uint32_t hw, lw;
                splitpack(esm[(2 * wr) * PE + n], esm[(2 * wr + 1) * PE + n], hw, lw);
                long long o = ((bm >> 1) + wr) * ldC + bn + n;
                Cbh[o] = hw; Cbl[o] = lw;
            }
        } else {
            // EPI_AT: transposed split store -> BT/A format [n][m/2]
            const int i = tid >> 2, j0 = (tid & 3) << 4;
#pragma unroll
            for (int j = 0; j < 16; j++) {
                int wc = j0 + j;
                uint32_t hw, lw;
                splitpack(esm[(2 * wc) * PE + i], esm[(2 * wc + 1) * PE + i], hw, lw);
                long long o = (bn + i) * ldC + (bm >> 1) + wc;
                Cbh[o] = hw; Cbl[o] = lw;
            }
        }
    }
}

// ---------------- input splitters ----------------
__global__ void __launch_bounds__(256)
split_wA(const float* __restrict__ src, uint32_t* __restrict__ h, uint32_t* __restrict__ l,
         long long nwords)
{
    long long i = blockIdx.x * 256ll + threadIdx.x;
    if (i >= nwords) return;
    float2 v = reinterpret_cast<const float2*>(src)[i];
    uint32_t hw, lw;
    splitpack(v.x, v.y, hw, lw);
    h[i] = hw;
    if (l) l[i] = lw;
}
__global__ void __launch_bounds__(256)
split_xB(const float* __restrict__ src, uint32_t* __restrict__ h, uint32_t* __restrict__ l,
         int ncols, long long nwords)
{
    long long i = blockIdx.x * 256ll + threadIdx.x;
    if (i >= nwords) return;
    long long wr = i / ncols, c = i - wr * ncols;
    float x0 = src[(2 * wr) * ncols + c];
    float x1 = src[(2 * wr + 1) * ncols + c];
    uint32_t hw, lw;
    splitpack(x0, x1, hw, lw);
    h[i] = hw; l[i] = lw;
}

// x [D][N] -> xT BT [N][D/2] (hi only). Block: 64 d x 32 n tile.
__global__ void __launch_bounds__(256)
xsplitT(const float* __restrict__ x, uint32_t* __restrict__ h)
{
    __shared__ float t[64][33];
    const int bn0 = blockIdx.x << 5;
    const int bd0 = blockIdx.y << 6;
    const long long xb = (long long)blockIdx.z * DDIM * NSEQ;
    const long long ob = (long long)blockIdx.z * NSEQ * (DDIM / 2);
    const int tid = threadIdx.x;
#pragma unroll
    for (int i = 0; i < 8; i++) {
        int e = tid + (i << 8);
        int r = e >> 5, c = e & 31;
        t[r][c] = x[xb + (long long)(bd0 + r) * NSEQ + bn0 + c];
    }
    __syncthreads();
#pragma unroll
    for (int i = 0; i < 4; i++) {
        int e = tid + (i << 8);
        int n = e >> 5, dw = e & 31;
        h[ob + (long long)(bn0 + n) * (DDIM / 2) + (bd0 >> 1) + dw]
            = pack2(t[2 * dw][n], t[2 * dw + 1][n]);
    }
}

// word transpose: in [NSEQ/2][NSEQ] words -> out [NSEQ][NSEQ/2]
__global__ void __launch_bounds__(256)
wtrans(const uint32_t* __restrict__ in, uint32_t* __restrict__ out)
{
    __shared__ uint32_t t[32][33];
    const int R = NSEQ / 2, C = NSEQ;
    const int bc = blockIdx.x << 5;
    const int br = blockIdx.y << 5;
    const long long ib = (long long)blockIdx.z * R * C;
    const long long ob = (long long)blockIdx.z * C * R;
    const int tid = threadIdx.x;
#pragma unroll
    for (int i = 0; i < 4; i++) {
        int e = tid + (i << 8);
        int r = e >> 5, c = e & 31;
        t[r][c] = in[ib + (long long)(br + r) * C + bc + c];
    }
    __syncthreads();
#pragma unroll
    for (int i = 0; i < 4; i++) {
        int e = tid + (i << 8);
        int r = e >> 5, c = e & 31;
        out[ob + (long long)(bc + r) * R + br + c] = t[c][r];
    }
}

// ---------------- softmax on row pairs, packed output [i/2][j] ----------------
__global__ void __launch_bounds__(256)
softmax2(const float* __restrict__ S, uint32_t* __restrict__ Sh, int N)
{
    const float* r0 = S + (long long)(2 * blockIdx.x) * N;
    const float* r1 = r0 + N;
    uint32_t* oh = Sh + (long long)blockIdx.x * N;
    const int tid = threadIdx.x;
    __shared__ float red0[256], red1[256];

    float v0[8], v1[8];
    float m0 = -3.4e38f, m1 = -3.4e38f;
#pragma unroll
    for (int i = 0; i < 8; i++) {
        int j = tid + (i << 8);
        v0[i] = r0[j]; v1[i] = r1[j];
        m0 = fmaxf(m0, v0[i]); m1 = fmaxf(m1, v1[i]);
    }
    red0[tid] = m0; red1[tid] = m1;
    __syncthreads();
    for (int s = 128; s > 0; s >>= 1) {
        if (tid < s) {
            red0[tid] = fmaxf(red0[tid], red0[tid + s]);
            red1[tid] = fmaxf(red1[tid], red1[tid + s]);
        }
        __syncthreads();
    }
    m0 = red0[0]; m1 = red1[0];
    __syncthreads();

    float s0 = 0.0f, s1 = 0.0f;
#pragma unroll
    for (int i = 0; i < 8; i++) {
        v0[i] = __expf(v0[i] - m0); s0 += v0[i];
        v1[i] = __expf(v1[i] - m1); s1 += v1[i];
    }
    red0[tid] = s0; red1[tid] = s1;
    __syncthreads();
    for (int s = 128; s > 0; s >>= 1) {
        if (tid < s) { red0[tid] += red0[tid + s]; red1[tid] += red1[tid + s]; }
        __syncthreads();
    }
    float i0 = 1.0f / red0[0], i1 = 1.0f / red1[0];
#pragma unroll
    for (int i = 0; i < 8; i++) {
        int j = tid + (i << 8);
        oh[j] = pack2(v0[i] * i0, v1[i] * i1);
    }
}

extern "C" void kernel_launch(void* const* d_in, const int* in_sizes, int n_in,
                              void* d_out, int out_size)
{
    const float* x   = (const float*)d_in[0];
    const float* W_Q = (const float*)d_in[1];
    const float* W_K = (const float*)d_in[2];
    const float* W_V = (const float*)d_in[3];
    const float* W_O = (const float*)d_in[4];
    float*       out = (float*)d_out;

    uint32_t *xBh,*xBl,*xTh,*wqh,*wql,*wkh,*wkl,*wvh,*woh;
    uint32_t *qBh,*qBl,*ktAh,*ktAl,*vAh,*vAl,*sBh,*sT,*aTh,*aTl;
    float *s;
    cudaGetSymbolAddress((void**)&xBh, g_xBh); cudaGetSymbolAddress((void**)&xBl, g_xBl);
    cudaGetSymbolAddress((void**)&xTh, g_xTh);
    cudaGetSymbolAddress((void**)&wqh, g_wqh); cudaGetSymbolAddress((void**)&wql, g_wql);
    cudaGetSymbolAddress((void**)&wkh, g_wkh); cudaGetSymbolAddress((void**)&wkl, g_wkl);
    cudaGetSymbolAddress((void**)&wvh, g_wvh);
    cudaGetSymbolAddress((void**)&woh, g_woh);
    cudaGetSymbolAddress((void**)&qBh, g_qBh); cudaGetSymbolAddress((void**)&qBl, g_qBl);
    cudaGetSymbolAddress((void**)&ktAh, g_ktAh); cudaGetSymbolAddress((void**)&ktAl, g_ktAl);
    cudaGetSymbolAddress((void**)&vAh, g_vAh); cudaGetSymbolAddress((void**)&vAl, g_vAl);
    cudaGetSymbolAddress((void**)&s,   g_s);
    cudaGetSymbolAddress((void**)&sBh, g_sBh); cudaGetSymbolAddress((void**)&sT, g_sT);
    cudaGetSymbolAddress((void**)&aTh, g_aTh); cudaGetSymbolAddress((void**)&aTl, g_aTl);

    cudaFuncSetAttribute((const void*)gemm16<EPI_B,3,false>,     cudaFuncAttributeMaxDynamicSharedMemorySize, SMEM_BYTES);
    cudaFuncSetAttribute((const void*)gemm16<EPI_AT,3,false>,    cudaFuncAttributeMaxDynamicSharedMemorySize, SMEM_BYTES);
    cudaFuncSetAttribute((const void*)gemm16<EPI_PLAIN,3,false>, cudaFuncAttributeMaxDynamicSharedMemorySize, SMEM_BYTES);
    cudaFuncSetAttribute((const void*)gemm16<EPI_A,1,true>,      cudaFuncAttributeMaxDynamicSharedMemorySize, SMEM_BYTES);
    cudaFuncSetAttribute((const void*)gemm16<EPI_AT,1,true>,     cudaFuncAttributeMaxDynamicSharedMemorySize, SMEM_BYTES);
    cudaFuncSetAttribute((const void*)gemm16<EPI_PLAIN,1,true>,  cudaFuncAttributeMaxDynamicSharedMemorySize, SMEM_BYTES);

    const long long xBb = (long long)(DDIM/2) * NSEQ;
    const long long xTb = (long long)NSEQ * (DDIM/2);
    const long long qBb = (long long)(MH/2) * NSEQ;
    const long long ktb = (long long)NSEQ * (MH/2);
    const long long vAb = (long long)MV * (NSEQ/2);
    const long long sTb = (long long)NSEQ * (NSEQ/2);
    const long long aTb = (long long)NSEQ * (MV/2);
    const long long sFb = (long long)NSEQ * NSEQ;
    const long long oFb = (long long)DDIM * NSEQ;

    // ---- split inputs ----
    split_wA<<<(MH * DDIM / 2 + 255) / 256, 256>>>(W_Q, wqh, wql, (long long)MH * DDIM / 2);
    split_wA<<<(MH * DDIM / 2 + 255) / 256, 256>>>(W_K, wkh, wkl, (long long)MH * DDIM / 2);
    split_wA<<<(MV * DDIM / 2 + 255) / 256, 256>>>(W_V, wvh, nullptr, (long long)MV * DDIM / 2);
    split_wA<<<(DDIM * MV / 2 + 255) / 256, 256>>>(W_O, woh, nullptr, (long long)DDIM * MV / 2);
    for (int b = 0; b < BATCH; b++)
        split_xB<<<((DDIM/2) * NSEQ + 255) / 256, 256>>>(
            x + (long long)b * DDIM * NSEQ, xBh + b * xBb, xBl + b * xBb,
            NSEQ, (long long)(DDIM/2) * NSEQ);
    {
        dim3 g(NSEQ / 32, DDIM / 64, BATCH);
        xsplitT<<<g, 256>>>(x, xTh);
    }

    // ---- projections ----
    {
        dim3 g(NSEQ / 64, MH / 128, BATCH);
        // Q (3-product, B-format out)
        gemm16<EPI_B,3,false><<<g, 256, SMEM_BYTES>>>(wqh, wql, xBh, xBl, nullptr, qBh, qBl,
                                                      DDIM, DDIM/2, NSEQ, NSEQ, 0, xBb, qBb);
        // K^T (3-product, A-format out)
        gemm16<EPI_AT,3,false><<<g, 256, SMEM_BYTES>>>(wkh, wkl, xBh, xBl, nullptr, ktAh, ktAl,
                                                       DDIM, DDIM/2, NSEQ, MH/2, 0, xBb, ktb);
        // V (1-product, BT B = x^T, A-format out)
        gemm16<EPI_A,1,true><<<g, 256, SMEM_BYTES>>>(wvh, nullptr, xTh, nullptr, nullptr, vAh, vAl,
                                                     DDIM, DDIM/2, DDIM/2, NSEQ/2, 0, xTb, vAb);
    }
    // ---- scores (3-product, plain fp32 out) ----
    {
        dim3 g(NSEQ / 64, NSEQ / 128, BATCH);
        gemm16<EPI_PLAIN,3,false><<<g, 256, SMEM_BYTES>>>(ktAh, ktAl, qBh, qBl, s, nullptr, nullptr,
                                                          MH, MH/2, NSEQ, NSEQ, ktb, qBb, sFb);
    }
    softmax2<<<BATCH * NSEQ / 2, 256>>>(s, sBh, NSEQ);
    {
        dim3 g(NSEQ / 32, (NSEQ / 2) / 32, BATCH);
        wtrans<<<g, 256>>>(sBh, sT);
    }
    // ---- attn = V @ S (1-product, BT B = S^T, BT out via EPI_AT) ----
    {
        dim3 g(NSEQ / 64, MV / 128, BATCH);
        gemm16<EPI_AT,1,true><<<g, 256, SMEM_BYTES>>>(vAh, nullptr, sT, nullptr, nullptr, aTh, aTl,
                                                      NSEQ, NSEQ/2, NSEQ/2, MV/2, vAb, sTb, aTb);
    }
    // ---- out = W_O @ attn (1-product, BT B = attn^T, plain out) ----
    {
        dim3 g(NSEQ / 64, DDIM / 128, BATCH);
        gemm16<EPI_PLAIN,1,true><<<g, 256, SMEM_BYTES>>>(woh, nullptr, aTh, nullptr, out, nullptr, nullptr,
                                                         MV, MV/2, MV/2, NSEQ, 0, aTb, oFb);
    }
}

// round 17
// speedup vs baseline: 1.0785x; 1.0785x over previous
#include <cuda_runtime.h>
#include <cuda_fp16.h>
#include <cstdint>

// ---------------------------------------------------------------------------
// SelfAttention on GB300 (sm_103 base target).
// R17: R15 (best) with smem layout reordered so hi-regions are contiguous:
// NPROD=1 kernels allocate only the hi half (53KB) and run 3 CTAs/SM
// (__launch_bounds__ cap 84 regs); NPROD=3 kernels identical to R15 (2 CTAs).
// ---------------------------------------------------------------------------

#define BATCH 4
#define DDIM  1024
#define NSEQ  2048
#define MH    1024
#define MV    1024

// ---- packed global scratch (uint32 = f16x2). Allocation-free contract. ----
__device__ __align__(256) uint32_t g_xBh[(size_t)BATCH * (DDIM/2) * NSEQ];
__device__ __align__(256) uint32_t g_xBl[(size_t)BATCH * (DDIM/2) * NSEQ];
__device__ __align__(256) uint32_t g_wqh[(size_t)MH * (DDIM/2)];
__device__ __align__(256) uint32_t g_wql[(size_t)MH * (DDIM/2)];
__device__ __align__(256) uint32_t g_wkh[(size_t)MH * (DDIM/2)];
__device__ __align__(256) uint32_t g_wkl[(size_t)MH * (DDIM/2)];
__device__ __align__(256) uint32_t g_wvh[(size_t)MV * (DDIM/2)];
__device__ __align__(256) uint32_t g_woh[(size_t)DDIM * (MV/2)];
__device__ __align__(256) uint32_t g_qBh[(size_t)BATCH * (MH/2) * NSEQ];
__device__ __align__(256) uint32_t g_qBl[(size_t)BATCH * (MH/2) * NSEQ];
__device__ __align__(256) uint32_t g_ktAh[(size_t)BATCH * NSEQ * (MH/2)];
__device__ __align__(256) uint32_t g_ktAl[(size_t)BATCH * NSEQ * (MH/2)];
__device__ __align__(256) uint32_t g_vAh[(size_t)BATCH * MV * (NSEQ/2)];
__device__ __align__(256) uint32_t g_vAl[(size_t)BATCH * MV * (NSEQ/2)];
__device__ __align__(256) float    g_s[(size_t)BATCH * NSEQ * NSEQ];
__device__ __align__(256) uint32_t g_sBh[(size_t)BATCH * (NSEQ/2) * NSEQ];
__device__ __align__(256) uint32_t g_aBh[(size_t)BATCH * (MV/2) * NSEQ];
__device__ __align__(256) uint32_t g_aBl[(size_t)BATCH * (MV/2) * NSEQ];

// ---- helpers ----
__device__ __forceinline__ uint32_t pack2(float a, float b) {
    __half2 h = __halves2half2(__float2half_rn(a), __float2half_rn(b));
    return *reinterpret_cast<uint32_t*>(&h);
}
__device__ __forceinline__ void splitpack(float x0, float x1, uint32_t& hw, uint32_t& lw) {
    float h0 = __half2float(__float2half_rn(x0));
    float h1 = __half2float(__float2half_rn(x1));
    hw = pack2(h0, h1);
    lw = pack2(x0 - h0, x1 - h1);
}
__device__ __forceinline__ void mma_f16(float* c, const uint32_t* a, const uint32_t* b) {
    asm volatile(
        "mma.sync.aligned.m16n8k16.row.col.f32.f16.f16.f32 "
        "{%0,%1,%2,%3}, {%4,%5,%6,%7}, {%8,%9}, {%0,%1,%2,%3};"
        : "+f"(c[0]), "+f"(c[1]), "+f"(c[2]), "+f"(c[3])
        : "r"(a[0]), "r"(a[1]), "r"(a[2]), "r"(a[3]), "r"(b[0]), "r"(b[1]));
}
__device__ __forceinline__ void ldsm_x4(uint32_t* r, uint32_t addr) {
    asm volatile("ldmatrix.sync.aligned.m8n8.x4.shared.b16 {%0,%1,%2,%3}, [%4];"
        : "=r"(r[0]), "=r"(r[1]), "=r"(r[2]), "=r"(r[3]) : "r"(addr));
}
__device__ __forceinline__ uint32_t smem_u32(const void* p) {
    uint32_t a;
    asm("{ .reg .u64 t; cvta.to.shared.u64 t, %1; cvt.u32.u64 %0, t; }" : "=r"(a) : "l"(p));
    return a;
}
__device__ __forceinline__ void cpa16(uint32_t d, const void* s) {
    asm volatile("cp.async.cg.shared.global [%0], [%1], 16;" :: "r"(d), "l"(s));
}

// ---- smem layout (word offsets), Kchunk = 128 elems = 64 words.
//      Hi regions FIRST so NPROD=1 can allocate only [0, SMEM_WORDS_1). ----
#define PAW 68      // A pitch: 64 words + 4 pad (ldsm CF: 272B = 17*16B)
#define PBW 72      // B pitch: 64 + 8 pad (scalar frag conflict-free)
#define SA_H 0
#define SB_H 8704            // 128*68
#define SMEM_WORDS_1 13312   // + 64*72 -> hi-only footprint
#define SA_L 13312
#define SB_L 22016           // + 128*68
#define SMEM_WORDS_3 26624
#define SMEM_BYTES_1 (SMEM_WORDS_1 * 4)   // 53248 -> 3 CTAs/SM
#define SMEM_BYTES_3 (SMEM_WORDS_3 * 4)   // 106496 -> 2 CTAs/SM

// Epilogue modes
#define EPI_PLAIN 0
#define EPI_A     1
#define EPI_B     2
#define EPI_AT    3

// ---------------------------------------------------------------------------
// C[m,n] = sum_k A(m,k)B(k,n); packed f16x2 hi/lo operands.
// A: [m][k/2] words (stride sAw); B: [k/2][n] words (stride sBw).
// NPROD = 3: hi*hi + hi*lo + lo*hi (2 CTAs/SM).  NPROD = 1: hi*hi (3 CTAs/SM).
// Tile 128(M) x 64(N) x 128(K). 256 thr, 8 warps (4m x 2n), warp tile 32x32.
// ---------------------------------------------------------------------------
template <int EPI, int NPROD>
__global__ void __launch_bounds__(256, (NPROD == 1) ? 3 : 2)
gemm17(const uint32_t* __restrict__ Ah, const uint32_t* __restrict__ Al,
       const uint32_t* __restrict__ Bh, const uint32_t* __restrict__ Bl,
       float* __restrict__ Cf, uint32_t* __restrict__ Ch, uint32_t* __restrict__ Cl,
       int K, long long sAw, long long sBw, long long ldC,
       long long bA, long long bB, long long bC)
{
    extern __shared__ uint32_t smw[];
    const uint32_t smb = smem_u32(smw);

    const int tid = threadIdx.x, wid = tid >> 5, lane = tid & 31;
    const int gid = lane >> 2, tig = lane & 3;
    const int wm = (wid & 3) << 5;
    const int wn = (wid >> 2) << 5;

    const uint32_t* Abh = Ah + (long long)blockIdx.z * bA;
    const uint32_t* Abl = (NPROD == 3) ? Al + (long long)blockIdx.z * bA : nullptr;
    const uint32_t* Bbh = Bh + (long long)blockIdx.z * bB;
    const uint32_t* Bbl = (NPROD == 3) ? Bl + (long long)blockIdx.z * bB : nullptr;
    const long long bm = (long long)blockIdx.y << 7;
    const long long bn = (long long)blockIdx.x << 6;

    const int lrow = (lane & 7) + (((lane >> 3) & 1) << 3);
    const int lcol = ((lane >> 4) & 1) << 2;

    float acc[2][4][4];
#pragma unroll
    for (int mt = 0; mt < 2; mt++)
#pragma unroll
        for (int nt = 0; nt < 4; nt++)
#pragma unroll
            for (int r = 0; r < 4; r++) acc[mt][nt][r] = 0.0f;

    const int nch = K >> 7;            // Kchunk = 128 elems = 64 words
    for (int ic = 0; ic < nch; ic++) {
        const long long k0w = (long long)ic << 6;

        // ---- A tile: 128 rows x 64 words ----
#pragma unroll
        for (int i = 0; i < 8; i++) {
            int idx = tid + (i << 8);
            int row = idx >> 4, g4 = (idx & 15) << 2;
            uint32_t d = smb + (uint32_t)((SA_H + row * PAW + g4) << 2);
            cpa16(d, Abh + (bm + row) * sAw + k0w + g4);
            if (NPROD == 3)
                cpa16(d + ((SA_L - SA_H) << 2), Abl + (bm + row) * sAw + k0w + g4);
        }
        // ---- B tile: 64 word-rows x 64 words ----
#pragma unroll
        for (int i = 0; i < 4; i++) {
            int idx = tid + (i << 8);
            int wr = idx >> 4, g4 = (idx & 15) << 2;
            uint32_t d = smb + (uint32_t)((SB_H + wr * PBW + g4) << 2);
            cpa16(d, Bbh + (k0w + wr) * sBw + bn + g4);
            if (NPROD == 3)
                cpa16(d + ((SB_L - SB_H) << 2), Bbl + (k0w + wr) * sBw + bn + g4);
        }
        asm volatile("cp.async.commit_group;" ::: "memory");
        asm volatile("cp.async.wait_group 0;" ::: "memory");
        __syncthreads();

#pragma unroll
        for (int ks = 0; ks < 8; ks++) {
            const int kb = ks << 3;
            uint32_t ah[2][4], al[2][4], bh[4][2], bl[4][2];
#pragma unroll
            for (int mt = 0; mt < 2; mt++) {
                int row = wm + (mt << 4) + lrow;
                uint32_t ad = smb + (uint32_t)((SA_H + row * PAW + kb + lcol) << 2);
                ldsm_x4(ah[mt], ad);
                if (NPROD == 3) ldsm_x4(al[mt], ad + ((SA_L - SA_H) << 2));
            }
#pragma unroll
            for (int nt = 0; nt < 4; nt++) {
                int cc = wn + (nt << 3) + gid;
                bh[nt][0] = smw[SB_H + (kb + tig) * PBW + cc];
                bh[nt][1] = smw[SB_H + (kb + tig + 4) * PBW + cc];
                if (NPROD == 3) {
                    bl[nt][0] = smw[SB_L + (kb + tig) * PBW + cc];
                    bl[nt][1] = smw[SB_L + (kb + tig + 4) * PBW + cc];
                }
            }
#pragma unroll
            for (int mt = 0; mt < 2; mt++)
#pragma unroll
                for (int nt = 0; nt < 4; nt++) mma_f16(acc[mt][nt], ah[mt], bh[nt]);
            if (NPROD == 3) {
#pragma unroll
                for (int mt = 0; mt < 2; mt++)
#pragma unroll
                    for (int nt = 0; nt < 4; nt++) mma_f16(acc[mt][nt], ah[mt], bl[nt]);
#pragma unroll
                for (int mt = 0; mt < 2; mt++)
#pragma unroll
                    for (int nt = 0; nt < 4; nt++) mma_f16(acc[mt][nt], al[mt], bh[nt]);
            }
        }
        __syncthreads();
    }

    // ---------------- epilogues (identical to R15) ----------------
    if (EPI == EPI_PLAIN) {
        float* Cb = Cf + (long long)blockIdx.z * bC;
#pragma unroll
        for (int mt = 0; mt < 2; mt++) {
            long long r0 = bm + wm + (mt << 4) + gid;
#pragma unroll
            for (int nt = 0; nt < 4; nt++) {
                long long cc = bn + wn + (nt << 3) + (tig << 1);
                *reinterpret_cast<float2*>(Cb + r0 * ldC + cc)       = make_float2(acc[mt][nt][0], acc[mt][nt][1]);
                *reinterpret_cast<float2*>(Cb + (r0 + 8) * ldC + cc) = make_float2(acc[mt][nt][2], acc[mt][nt][3]);
            }
        }
    } else if (EPI == EPI_A) {
        uint32_t* Cbh = Ch + (long long)blockIdx.z * bC;
        uint32_t* Cbl = Cl + (long long)blockIdx.z * bC;
#pragma unroll
        for (int mt = 0; mt < 2; mt++) {
            long long r0 = bm + wm + (mt << 4) + gid;
#pragma unroll
            for (int nt = 0; nt < 4; nt++) {
                long long wc = (bn + wn + (nt << 3) + (tig << 1)) >> 1;
                uint32_t hw, lw;
                splitpack(acc[mt][nt][0], acc[mt][nt][1], hw, lw);
                Cbh[r0 * ldC + wc] = hw; Cbl[r0 * ldC + wc] = lw;
                splitpack(acc[mt][nt][2], acc[mt][nt][3], hw, lw);
                Cbh[(r0 + 8) * ldC + wc] = hw; Cbl[(r0 + 8) * ldC + wc] = lw;
            }
        }
    } else {
        float* esm = reinterpret_cast<float*>(smw);   // [128m][pitch 65] = 8320 words, fits hi region
        const int PE = 65;
#pragma unroll
        for (int mt = 0; mt < 2; mt++) {
            int r = wm + (mt << 4) + gid;
#pragma unroll
            for (int nt = 0; nt < 4; nt++) {
                int c = wn + (nt << 3) + (tig << 1);
                esm[r * PE + c]           = acc[mt][nt][0];
                esm[r * PE + c + 1]       = acc[mt][nt][1];
                esm[(r + 8) * PE + c]     = acc[mt][nt][2];
                esm[(r + 8) * PE + c + 1] = acc[mt][nt][3];
            }
        }
        __syncthreads();
        uint32_t* Cbh = Ch + (long long)blockIdx.z * bC;
        uint32_t* Cbl = Cl + (long long)blockIdx.z * bC;
        if (EPI == EPI_B) {
            const int n = tid & 63, grp = tid >> 6;
#pragma unroll
            for (int j = 0; j < 16; j++) {
                int wr = grp * 16 + j;
                uint32_t hw, lw;
                splitpack(esm[(2 * wr) * PE + n], esm[(2 * wr + 1) * PE + n], hw, lw);
                long long o = ((bm >> 1) + wr) * ldC + bn + n;
                Cbh[o] = hw; Cbl[o] = lw;
            }
        } else {
            const int i = tid >> 2, j0 = (tid & 3) << 4;
#pragma unroll
            for (int j = 0; j < 16; j++) {
                int wc = j0 + j;
                uint32_t hw, lw;
                splitpack(esm[(2 * wc) * PE + i], esm[(2 * wc + 1) * PE + i], hw, lw);
                long long o = (bn + i) * ldC + (bm >> 1) + wc;
                Cbh[o] = hw; Cbl[o] = lw;
            }
        }
    }
}

// ---------------- input splitters ----------------
__global__ void __launch_bounds__(256)
split_wA(const float* __restrict__ src, uint32_t* __restrict__ h, uint32_t* __restrict__ l,
         long long nwords)
{
    long long i = blockIdx.x * 256ll + threadIdx.x;
    if (i >= nwords) return;
    float2 v = reinterpret_cast<const float2*>(src)[i];
    uint32_t hw, lw;
    splitpack(v.x, v.y, hw, lw);
    h[i] = hw;
    if (l) l[i] = lw;
}
__global__ void __launch_bounds__(256)
split_xB(const float* __restrict__ src, uint32_t* __restrict__ h, uint32_t* __restrict__ l,
         int ncols, long long nwords)
{
    long long i = blockIdx.x * 256ll + threadIdx.x;
    if (i >= nwords) return;
    long long wr = i / ncols, c = i - wr * ncols;
    float x0 = src[(2 * wr) * ncols + c];
    float x1 = src[(2 * wr + 1) * ncols + c];
    uint32_t hw, lw;
    splitpack(x0, x1, hw, lw);
    h[i] = hw; l[i] = lw;
}

// ---------------- softmax on row pairs, packed B-format (hi only) ----------------
__global__ void __launch_bounds__(256)
softmax2(const float* __restrict__ S, uint32_t* __restrict__ Sh, int N)
{
    const float* r0 = S + (long long)(2 * blockIdx.x) * N;
    const float* r1 = r0 + N;
    uint32_t* oh = Sh + (long long)blockIdx.x * N;
    const int tid = threadIdx.x;
    __shared__ float red0[256], red1[256];

    float v0[8], v1[8];
    float m0 = -3.4e38f, m1 = -3.4e38f;
#pragma unroll
    for (int i = 0; i < 8; i++) {
        int j = tid + (i << 8);
        v0[i] = r0[j]; v1[i] = r1[j];
        m0 = fmaxf(m0, v0[i]); m1 = fmaxf(m1, v1[i]);
    }
    red0[tid] = m0; red1[tid] = m1;
    __syncthreads();
    for (int s = 128; s > 0; s >>= 1) {
        if (tid < s) {
            red0[tid] = fmaxf(red0[tid], red0[tid + s]);
            red1[tid] = fmaxf(red1[tid], red1[tid + s]);
        }
        __syncthreads();
    }
    m0 = red0[0]; m1 = red1[0];
    __syncthreads();

    float s0 = 0.0f, s1 = 0.0f;
#pragma unroll
    for (int i = 0; i < 8; i++) {
        v0[i] = __expf(v0[i] - m0); s0 += v0[i];
        v1[i] = __expf(v1[i] - m1); s1 += v1[i];
    }
    red0[tid] = s0; red1[tid] = s1;
    __syncthreads();
    for (int s = 128; s > 0; s >>= 1) {
        if (tid < s) { red0[tid] += red0[tid + s]; red1[tid] += red1[tid + s]; }
        __syncthreads();
    }
    float i0 = 1.0f / red0[0], i1 = 1.0f / red1[0];
#pragma unroll
    for (int i = 0; i < 8; i++) {
        int j = tid + (i << 8);
        oh[j] = pack2(v0[i] * i0, v1[i] * i1);
    }
}

extern "C" void kernel_launch(void* const* d_in, const int* in_sizes, int n_in,
                              void* d_out, int out_size)
{
    const float* x   = (const float*)d_in[0];
    const float* W_Q = (const float*)d_in[1];
    const float* W_K = (const float*)d_in[2];
    const float* W_V = (const float*)d_in[3];
    const float* W_O = (const float*)d_in[4];
    float*       out = (float*)d_out;

    uint32_t *xBh,*xBl,*wqh,*wql,*wkh,*wkl,*wvh,*woh;
    uint32_t *qBh,*qBl,*ktAh,*ktAl,*vAh,*vAl,*sBh,*aBh,*aBl;
    float *s;
    cudaGetSymbolAddress((void**)&xBh, g_xBh); cudaGetSymbolAddress((void**)&xBl, g_xBl);
    cudaGetSymbolAddress((void**)&wqh, g_wqh); cudaGetSymbolAddress((void**)&wql, g_wql);
    cudaGetSymbolAddress((void**)&wkh, g_wkh); cudaGetSymbolAddress((void**)&wkl, g_wkl);
    cudaGetSymbolAddress((void**)&wvh, g_wvh);
    cudaGetSymbolAddress((void**)&woh, g_woh);
    cudaGetSymbolAddress((void**)&qBh, g_qBh); cudaGetSymbolAddress((void**)&qBl, g_qBl);
    cudaGetSymbolAddress((void**)&ktAh, g_ktAh); cudaGetSymbolAddress((void**)&ktAl, g_ktAl);
    cudaGetSymbolAddress((void**)&vAh, g_vAh); cudaGetSymbolAddress((void**)&vAl, g_vAl);
    cudaGetSymbolAddress((void**)&s,   g_s);
    cudaGetSymbolAddress((void**)&sBh, g_sBh);
    cudaGetSymbolAddress((void**)&aBh, g_aBh); cudaGetSymbolAddress((void**)&aBl, g_aBl);

    cudaFuncSetAttribute(gemm17<EPI_B,3>,     cudaFuncAttributeMaxDynamicSharedMemorySize, SMEM_BYTES_3);
    cudaFuncSetAttribute(gemm17<EPI_AT,3>,    cudaFuncAttributeMaxDynamicSharedMemorySize, SMEM_BYTES_3);
    cudaFuncSetAttribute(gemm17<EPI_PLAIN,3>, cudaFuncAttributeMaxDynamicSharedMemorySize, SMEM_BYTES_3);
    cudaFuncSetAttribute(gemm17<EPI_A,1>,     cudaFuncAttributeMaxDynamicSharedMemorySize, SMEM_BYTES_1);
    cudaFuncSetAttribute(gemm17<EPI_B,1>,     cudaFuncAttributeMaxDynamicSharedMemorySize, SMEM_BYTES_1);
    cudaFuncSetAttribute(gemm17<EPI_PLAIN,1>, cudaFuncAttributeMaxDynamicSharedMemorySize, SMEM_BYTES_1);

    const long long xBb = (long long)(DDIM/2) * NSEQ;
    const long long qBb = (long long)(MH/2) * NSEQ;
    const long long ktb = (long long)NSEQ * (MH/2);
    const long long vAb = (long long)MV * (NSEQ/2);
    const long long sBb = (long long)(NSEQ/2) * NSEQ;
    const long long aBb = (long long)(MV/2) * NSEQ;
    const long long sFb = (long long)NSEQ * NSEQ;
    const long long oFb = (long long)DDIM * NSEQ;

    // ---- split inputs (W_V, W_O: hi only) ----
    split_wA<<<(MH * DDIM / 2 + 255) / 256, 256>>>(W_Q, wqh, wql, (long long)MH * DDIM / 2);
    split_wA<<<(MH * DDIM / 2 + 255) / 256, 256>>>(W_K, wkh, wkl, (long long)MH * DDIM / 2);
    split_wA<<<(MV * DDIM / 2 + 255) / 256, 256>>>(W_V, wvh, nullptr, (long long)MV * DDIM / 2);
    split_wA<<<(DDIM * MV / 2 + 255) / 256, 256>>>(W_O, woh, nullptr, (long long)DDIM * MV / 2);
    for (int b = 0; b < BATCH; b++)
        split_xB<<<((DDIM/2) * NSEQ + 255) / 256, 256>>>(
            x + (long long)b * DDIM * NSEQ, xBh + b * xBb, xBl + b * xBb,
            NSEQ, (long long)(DDIM/2) * NSEQ);

    // ---- projections (Q/K 3-product, V 1-product) ----
    {
        dim3 g(NSEQ / 64, MH / 128, BATCH);
        gemm17<EPI_B,3><<<g, 256, SMEM_BYTES_3>>>(wqh, wql, xBh, xBl, nullptr, qBh, qBl,
                                                  DDIM, DDIM/2, NSEQ, NSEQ, 0, xBb, qBb);
        gemm17<EPI_AT,3><<<g, 256, SMEM_BYTES_3>>>(wkh, wkl, xBh, xBl, nullptr, ktAh, ktAl,
                                                   DDIM, DDIM/2, NSEQ, MH/2, 0, xBb, ktb);
        gemm17<EPI_A,1><<<g, 256, SMEM_BYTES_1>>>(wvh, nullptr, xBh, nullptr, nullptr, vAh, vAl,
                                                  DDIM, DDIM/2, NSEQ, NSEQ/2, 0, xBb, vAb);
    }
    // ---- scores (3-product, plain out) ----
    {
        dim3 g(NSEQ / 64, NSEQ / 128, BATCH);
        gemm17<EPI_PLAIN,3><<<g, 256, SMEM_BYTES_3>>>(ktAh, ktAl, qBh, qBl, s, nullptr, nullptr,
                                                      MH, MH/2, NSEQ, NSEQ, ktb, qBb, sFb);
    }
    softmax2<<<BATCH * NSEQ / 2, 256>>>(s, sBh, NSEQ);
    // ---- attn = V @ S (1-product) ----
    {
        dim3 g(NSEQ / 64, MV / 128, BATCH);
        gemm17<EPI_B,1><<<g, 256, SMEM_BYTES_1>>>(vAh, nullptr, sBh, nullptr, nullptr, aBh, aBl,
                                                  NSEQ, NSEQ/2, NSEQ, NSEQ, vAb, sBb, aBb);
    }
    // ---- out = W_O @ attn (1-product) ----
    {
        dim3 g(NSEQ / 64, DDIM / 128, BATCH);
        gemm17<EPI_PLAIN,1><<<g, 256, SMEM_BYTES_1>>>(woh, nullptr, aBh, nullptr, out, nullptr, nullptr,
                                                      MV, MV/2, NSEQ, NSEQ, 0, aBb, oFb);
    }
}